// round 8
// baseline (speedup 1.0000x reference)
#include <cuda_runtime.h>

// Problem constants
#define BB 64      // batch
#define SS 256     // seq length
#define VV 2048    // ntokens
#define HH 512     // nhid
#define NCTA 148   // one CTA per SM (wave-1 resident => grid barrier is safe)
#define NTHR 512

// Scratch (no allocations allowed). Zero-initialized at module load.
// g_h1pre is re-zeroed each call by the idle CTAs in phase 3.
// g_h2pre is zeroed each call in phase 1 (before barrier 0).
__device__ float g_h1pre[BB * HH];   // gather-sum accumulator (pre bias/relu)
__device__ float g_h2pre[BB * HH];   // h1 @ W2 accumulator    (pre bias/relu)
// Monotonic generation barriers: each call adds exactly NCTA to each counter,
// so (v/NCTA+1)*NCTA is the release target regardless of replay count.
__device__ unsigned g_bar[2];

static __device__ __forceinline__ void fadd4(float4& a, const float4 b) {
    a.x += b.x; a.y += b.y; a.z += b.z; a.w += b.w;
}

// 256-bit gather load with L2 evict_last (pin W1's 32MB hot set in 126MB L2).
// sm_103a: evict_last requires .v4.b64/.v8.b32 -> load as 4x b64, unpack.
static __device__ __forceinline__ void ldg256_el(const void* p,
                                                 float4& lo, float4& hi) {
    unsigned long long u0, u1, u2, u3;
    asm("ld.global.nc.L2::evict_last.v4.b64 {%0,%1,%2,%3}, [%4];"
        : "=l"(u0), "=l"(u1), "=l"(u2), "=l"(u3) : "l"(p));
    lo.x = __uint_as_float((unsigned)u0); lo.y = __uint_as_float((unsigned)(u0 >> 32));
    lo.z = __uint_as_float((unsigned)u1); lo.w = __uint_as_float((unsigned)(u1 >> 32));
    hi.x = __uint_as_float((unsigned)u2); hi.y = __uint_as_float((unsigned)(u2 >> 32));
    hi.z = __uint_as_float((unsigned)u3); hi.w = __uint_as_float((unsigned)(u3 >> 32));
}

static __device__ __forceinline__ void grid_bar(int which) {
    __syncthreads();
    if (threadIdx.x == 0) {
        __threadfence();                               // release my phase's writes
        unsigned v = atomicAdd(&g_bar[which], 1u);
        unsigned tgt = (v / NCTA + 1u) * NCTA;
        unsigned cur;
        do {
            asm volatile("ld.acquire.gpu.global.u32 %0, [%1];"
                         : "=r"(cur) : "l"(&g_bar[which]) : "memory");
        } while (cur < tgt);
        __threadfence();                               // acquire for whole CTA
    }
    __syncthreads();
}

// ---------------------------------------------------------------------------
// Single persistent kernel: gather -> barrier -> GEMM1 -> barrier -> GEMM2.
// ---------------------------------------------------------------------------
__global__ void __launch_bounds__(NTHR, 1) k_fused(
        const int* __restrict__ x32,
        const float* __restrict__ W1,
        const float* __restrict__ b1,
        const float* __restrict__ W2,
        const float* __restrict__ b2,
        const float* __restrict__ W3,
        const float* __restrict__ b3,
        float* __restrict__ out) {
    const int t   = threadIdx.x;
    const int cta = blockIdx.x;

    __shared__ unsigned rb[32];
    __shared__ __align__(16) float4 red[7][64][2];   // 7 groups x 64 cols x 32B
    __shared__ float As[64][33];
    __shared__ __align__(16) float Bs[32][32];
    __shared__ int s_is64;

    // ---- Phase 1: housekeeping + gather --------------------------------
    for (int i = cta * NTHR + t; i < BB * HH; i += NCTA * NTHR)
        g_h2pre[i] = 0.0f;
    for (int i = cta * NTHR + t; i < BB * SS; i += NCTA * NTHR)
        out[i] = b3[i & (SS - 1)];

    // Index dtype detection: int64 -> odd 32-bit words of first 128 elems are 0.
    if (t == 0) s_is64 = 1;
    __syncthreads();
    if (t < 128 && x32[2 * t + 1] != 0) s_is64 = 0;   // racy same-value: fine
    __syncthreads();
    const int is64 = s_is64;

    const int col = t & 63;      // float8 column (H = 512 -> 64 x 8 floats)
    const int q   = t >> 6;      // position group 0..7 (4 positions each)

    // 512 gather tasks: task = (batch, 32-position split).
    for (int task = cta; task < BB * 8; task += NCTA) {
        const int b  = task >> 3;
        const int p0 = (task & 7) * 32;

        __syncthreads();          // protect rb/red from previous iteration
        if (t < 32) {
            unsigned tok;
            if (is64) tok = (unsigned)((const long long*)x32)[b * SS + p0 + t];
            else      tok = (unsigned)x32[b * SS + p0 + t];
            rb[t] = (tok + (unsigned)(p0 + t) * VV) << 9;   // * HH (floats)
        }
        __syncthreads();

        // 4 independent 32B loads in flight (128B/thread outstanding).
        const int pb = q * 4;
        float4 lo[4], hi[4];
        #pragma unroll
        for (int i = 0; i < 4; i++)
            ldg256_el((const char*)(W1 + rb[pb + i]) + col * 32, lo[i], hi[i]);

        float4 alo = lo[0], ahi = hi[0];
        #pragma unroll
        for (int i = 1; i < 4; i++) { fadd4(alo, lo[i]); fadd4(ahi, hi[i]); }

        if (q > 0) { red[q - 1][col][0] = alo; red[q - 1][col][1] = ahi; }
        __syncthreads();
        if (q == 0) {
            #pragma unroll
            for (int g = 0; g < 7; g++) {
                fadd4(alo, red[g][col][0]);
                fadd4(ahi, red[g][col][1]);
            }
            float* dst = &g_h1pre[b * HH + col * 8];
            atomicAdd(dst + 0, alo.x); atomicAdd(dst + 1, alo.y);
            atomicAdd(dst + 2, alo.z); atomicAdd(dst + 3, alo.w);
            atomicAdd(dst + 4, ahi.x); atomicAdd(dst + 5, ahi.y);
            atomicAdd(dst + 6, ahi.z); atomicAdd(dst + 7, ahi.w);
        }
    }

    grid_bar(0);

    // ---- Phase 2: h2pre += relu(h1pre+b1)(64x512) @ W2(512x512) --------
    // 128 tasks: 16 n-tiles (32) x 8 k-splits (64). CTAs 128..147 idle.
    if (cta < 128) {
        const int nb = (cta & 15) * 32;
        const int kb = (cta >> 4) * 64;
        const int m  = t >> 3;          // 0..63
        const int n4 = (t & 7) * 4;     // 0..28
        float acc[4] = {0.f, 0.f, 0.f, 0.f};

        for (int kk = 0; kk < 64; kk += 32) {
            __syncthreads();
            #pragma unroll
            for (int i = 0; i < 4; i++) {
                int idx = i * NTHR + t;
                int mm = idx >> 5, k = idx & 31;
                int kg = kb + kk + k;
                As[mm][k] = fmaxf(g_h1pre[mm * HH + kg] + b1[kg], 0.0f);
            }
            #pragma unroll
            for (int i = 0; i < 2; i++) {
                int idx = i * NTHR + t;
                int k = idx >> 5, n = idx & 31;
                Bs[k][n] = W2[(kb + kk + k) * HH + nb + n];
            }
            __syncthreads();
            #pragma unroll
            for (int k = 0; k < 32; k++) {
                float a = As[m][k];
                float4 b4 = *(const float4*)&Bs[k][n4];
                acc[0] += a * b4.x; acc[1] += a * b4.y;
                acc[2] += a * b4.z; acc[3] += a * b4.w;
            }
        }
        #pragma unroll
        for (int j = 0; j < 4; j++)
            atomicAdd(&g_h2pre[m * HH + nb + n4 + j], acc[j]);
    }

    grid_bar(1);

    // ---- Phase 3: out += relu(h2pre+b2)(64x512) @ W3(512x256) ----------
    // 128 tasks: 8 n-tiles (32) x 16 k-splits (32). CTAs 128..147 instead
    // reset g_h1pre for the next call (its last reader finished at bar 1).
    if (cta >= 128) {
        for (int i = (cta - 128) * NTHR + t; i < BB * HH; i += 20 * NTHR)
            g_h1pre[i] = 0.0f;
    } else {
        const int nb = (cta & 7) * 32;
        const int kb = (cta >> 3) * 32;
        const int m  = t >> 3;
        const int n4 = (t & 7) * 4;
        float acc[4] = {0.f, 0.f, 0.f, 0.f};

        __syncthreads();
        #pragma unroll
        for (int i = 0; i < 4; i++) {
            int idx = i * NTHR + t;
            int mm = idx >> 5, k = idx & 31;
            int kg = kb + k;
            As[mm][k] = fmaxf(g_h2pre[mm * HH + kg] + b2[kg], 0.0f);
        }
        #pragma unroll
        for (int i = 0; i < 2; i++) {
            int idx = i * NTHR + t;
            int k = idx >> 5, n = idx & 31;
            Bs[k][n] = W3[(kb + k) * SS + nb + n];
        }
        __syncthreads();
        #pragma unroll
        for (int k = 0; k < 32; k++) {
            float a = As[m][k];
            float4 b4 = *(const float4*)&Bs[k][n4];
            acc[0] += a * b4.x; acc[1] += a * b4.y;
            acc[2] += a * b4.z; acc[3] += a * b4.w;
        }
        #pragma unroll
        for (int j = 0; j < 4; j++)
            atomicAdd(&out[m * SS + nb + n4 + j], acc[j]);
    }
}

// ---------------------------------------------------------------------------
extern "C" void kernel_launch(void* const* d_in, const int* in_sizes, int n_in,
                              void* d_out, int out_size) {
    const int*   x  = (const int*)d_in[0];   // int32 or int64, detected on device
    const float* W1 = (const float*)d_in[1];
    const float* b1 = (const float*)d_in[2];
    const float* W2 = (const float*)d_in[3];
    const float* b2 = (const float*)d_in[4];
    const float* W3 = (const float*)d_in[5];
    const float* b3 = (const float*)d_in[6];
    float* out = (float*)d_out;

    k_fused<<<NCTA, NTHR>>>(x, W1, b1, W2, b2, W3, b3, out);
}

// round 11
// speedup vs baseline: 1.4962x; 1.4962x over previous
#include <cuda_runtime.h>

// Problem constants
#define BB 64      // batch
#define SS 256     // seq length
#define VV 2048    // ntokens
#define HH 512     // nhid
#define NSPLIT 8   // sequence splits for the gather
#define SP (SS / NSPLIT)   // positions per gather CTA = 32

// Scratch (no allocations). Zero-initialized at module load.
// g_h1pre's ==0 invariant is restored by k_gemm2 each call.
__device__ float g_h1pre[BB * HH];          // gather accumulator (pre bias/relu)
__device__ float g_h2part[8][BB][HH];       // GEMM1 K-split partials (no atomics)

// ---------------------------------------------------------------------------
// K1: gather partial-sum -> atomicAdd into g_h1pre.   (R4 config, proven)
// grid = (256, 8): x = 64 batches x 4 H-chunks, y = 8 seq-splits of 32.
// block = 128 threads (one h column each). y==0 slice also seeds out = b3.
// Handles both int64 and int32 index layouts (runtime-detected).
// ---------------------------------------------------------------------------
__global__ void k_gather(const int* __restrict__ x32,
                         const float* __restrict__ W1,
                         const float* __restrict__ b3,
                         float* __restrict__ out) {
    const int t = threadIdx.x;

    if (blockIdx.y == 0) {
        const int gid = blockIdx.x * 128 + t;        // 0..32767
        if (gid < BB * SS) out[gid] = b3[gid & (SS - 1)];
    }

    __shared__ int s_is64;
    if (t == 0) s_is64 = 1;
    __syncthreads();
    if (x32[2 * t + 1] != 0) s_is64 = 0;   // racy same-value store: fine
    __syncthreads();
    const int is64 = s_is64;

    const int b  = blockIdx.x >> 2;                   // batch
    const int h  = ((blockIdx.x & 3) << 7) | t;       // 0..511
    const int p0 = blockIdx.y * SP;                   // first position

    __shared__ unsigned rb[SP];
    if (t < SP) {
        unsigned tok;
        if (is64) tok = (unsigned)((const long long*)x32)[b * SS + p0 + t];
        else      tok = (unsigned)x32[b * SS + p0 + t];
        rb[t] = (tok + (unsigned)(p0 + t) * VV) << 9;   // * HH
    }
    __syncthreads();

    float a0 = 0.f, a1 = 0.f, a2 = 0.f, a3 = 0.f;
    #pragma unroll
    for (int p = 0; p < SP; p += 4) {
        a0 += W1[rb[p + 0] + h];
        a1 += W1[rb[p + 1] + h];
        a2 += W1[rb[p + 2] + h];
        a3 += W1[rb[p + 3] + h];
    }
    atomicAdd(&g_h1pre[b * HH + h], (a0 + a1) + (a2 + a3));
}

// ---------------------------------------------------------------------------
// K2: GEMM1 partial: g_h2part[kbs] = relu(h1pre+b1)[:, kb..] @ W2[kb.., nb..]
// grid = (16 n-tiles of 32, 8 k-splits of 64), block = 128 threads.
// Pure STG.128 epilogue -> zero atomics.  float4 staging everywhere.
// ---------------------------------------------------------------------------
__global__ void __launch_bounds__(128) k_gemm1(
        const float* __restrict__ b1,
        const float* __restrict__ W2) {
    const int nb  = blockIdx.x * 32;
    const int kbs = blockIdx.y;          // 0..7
    const int kb  = kbs * 64;
    const int t   = threadIdx.x;
    const int m4  = (t >> 3) * 4;        // 0..60
    const int n4  = (t & 7) * 4;         // 0..28

    __shared__ float As[64][33];
    __shared__ __align__(16) float Bs[32][32];

    float acc[4][4] = {};

    for (int kk = 0; kk < 64; kk += 32) {
        __syncthreads();
        #pragma unroll
        for (int i = 0; i < 4; i++) {           // As: 64x32, float4 loads
            int idx = i * 128 + t;
            int mm = idx >> 3, k4 = (idx & 7) * 4;
            int kg = kb + kk + k4;
            float4 v  = *(const float4*)&g_h1pre[mm * HH + kg];
            float4 bb = *(const float4*)&b1[kg];
            As[mm][k4 + 0] = fmaxf(v.x + bb.x, 0.f);
            As[mm][k4 + 1] = fmaxf(v.y + bb.y, 0.f);
            As[mm][k4 + 2] = fmaxf(v.z + bb.z, 0.f);
            As[mm][k4 + 3] = fmaxf(v.w + bb.w, 0.f);
        }
        #pragma unroll
        for (int i = 0; i < 2; i++) {           // Bs: 32x32, float4 loads
            int idx = i * 128 + t;
            int k = idx >> 3, nn4 = (idx & 7) * 4;
            *(float4*)&Bs[k][nn4] =
                *(const float4*)&W2[(kb + kk + k) * HH + nb + nn4];
        }
        __syncthreads();

        #pragma unroll
        for (int k = 0; k < 32; k++) {
            float4 b4 = *(const float4*)&Bs[k][n4];
            float a0 = As[m4 + 0][k];
            float a1 = As[m4 + 1][k];
            float a2 = As[m4 + 2][k];
            float a3 = As[m4 + 3][k];
            acc[0][0] += a0 * b4.x; acc[0][1] += a0 * b4.y; acc[0][2] += a0 * b4.z; acc[0][3] += a0 * b4.w;
            acc[1][0] += a1 * b4.x; acc[1][1] += a1 * b4.y; acc[1][2] += a1 * b4.z; acc[1][3] += a1 * b4.w;
            acc[2][0] += a2 * b4.x; acc[2][1] += a2 * b4.y; acc[2][2] += a2 * b4.z; acc[2][3] += a2 * b4.w;
            acc[3][0] += a3 * b4.x; acc[3][1] += a3 * b4.y; acc[3][2] += a3 * b4.z; acc[3][3] += a3 * b4.w;
        }
    }

    #pragma unroll
    for (int i = 0; i < 4; i++)                 // STG.128 epilogue, no atomics
        *(float4*)&g_h2part[kbs][m4 + i][nb + n4] =
            make_float4(acc[i][0], acc[i][1], acc[i][2], acc[i][3]);
}

// ---------------------------------------------------------------------------
// K3: GEMM2: out += relu(sum_p h2part[p] + b2)(64x512) @ W3(512x256), K-split.
// grid = (8 n-tiles of 32, 16 k-splits of 32), block = 128 threads.
// The 8-partial summation is fused into A-staging. Also resets g_h1pre
// (its last reader, K2, precedes this kernel in stream order).
// ---------------------------------------------------------------------------
__global__ void __launch_bounds__(128) k_gemm2(
        const float* __restrict__ b2,
        const float* __restrict__ W3,
        float* __restrict__ out) {
    const int nb = blockIdx.x * 32;
    const int kb = blockIdx.y * 32;
    const int t  = threadIdx.x;
    const int m4 = (t >> 3) * 4;
    const int n4 = (t & 7) * 4;

    // Reset g_h1pre: 128 CTAs x 128 threads -> 2 elems/thread.
    {
        const int base = (blockIdx.y * gridDim.x + blockIdx.x) * 128 + t;
        g_h1pre[base] = 0.0f;
        g_h1pre[base + 16384] = 0.0f;
    }

    __shared__ float As[64][33];
    __shared__ __align__(16) float Bs[32][32];

    float acc[4][4] = {};

    #pragma unroll
    for (int i = 0; i < 4; i++) {               // As = relu(sum partials + b2)
        int idx = i * 128 + t;
        int mm = idx >> 3, k4 = (idx & 7) * 4;
        int kg = kb + k4;
        float4 s = *(const float4*)&b2[kg];
        #pragma unroll
        for (int p = 0; p < 8; p++) {
            float4 v = *(const float4*)&g_h2part[p][mm][kg];
            s.x += v.x; s.y += v.y; s.z += v.z; s.w += v.w;
        }
        As[mm][k4 + 0] = fmaxf(s.x, 0.f);
        As[mm][k4 + 1] = fmaxf(s.y, 0.f);
        As[mm][k4 + 2] = fmaxf(s.z, 0.f);
        As[mm][k4 + 3] = fmaxf(s.w, 0.f);
    }
    #pragma unroll
    for (int i = 0; i < 2; i++) {               // Bs: 32x32 of W3
        int idx = i * 128 + t;
        int k = idx >> 3, nn4 = (idx & 7) * 4;
        *(float4*)&Bs[k][nn4] =
            *(const float4*)&W3[(kb + k) * SS + nb + nn4];
    }
    __syncthreads();

    #pragma unroll
    for (int k = 0; k < 32; k++) {
        float4 b4 = *(const float4*)&Bs[k][n4];
        float a0 = As[m4 + 0][k];
        float a1 = As[m4 + 1][k];
        float a2 = As[m4 + 2][k];
        float a3 = As[m4 + 3][k];
        acc[0][0] += a0 * b4.x; acc[0][1] += a0 * b4.y; acc[0][2] += a0 * b4.z; acc[0][3] += a0 * b4.w;
        acc[1][0] += a1 * b4.x; acc[1][1] += a1 * b4.y; acc[1][2] += a1 * b4.z; acc[1][3] += a1 * b4.w;
        acc[2][0] += a2 * b4.x; acc[2][1] += a2 * b4.y; acc[2][2] += a2 * b4.z; acc[2][3] += a2 * b4.w;
        acc[3][0] += a3 * b4.x; acc[3][1] += a3 * b4.y; acc[3][2] += a3 * b4.z; acc[3][3] += a3 * b4.w;
    }

    #pragma unroll
    for (int i = 0; i < 4; i++)
        #pragma unroll
        for (int j = 0; j < 4; j++)
            atomicAdd(&out[(m4 + i) * SS + nb + n4 + j], acc[i][j]);
}

// ---------------------------------------------------------------------------
extern "C" void kernel_launch(void* const* d_in, const int* in_sizes, int n_in,
                              void* d_out, int out_size) {
    const int*   x  = (const int*)d_in[0];   // int32 or int64, detected on device
    const float* W1 = (const float*)d_in[1];
    const float* b1 = (const float*)d_in[2];
    const float* W2 = (const float*)d_in[3];
    const float* b2 = (const float*)d_in[4];
    const float* W3 = (const float*)d_in[5];
    const float* b3 = (const float*)d_in[6];
    float* out = (float*)d_out;

    k_gather<<<dim3(256, NSPLIT), 128>>>(x, W1, b3, out);
    k_gemm1<<<dim3(16, 8), 128>>>(b1, W2);
    k_gemm2<<<dim3(8, 16), 128>>>(b2, W3, out);
}